// round 4
// baseline (speedup 1.0000x reference)
#include <cuda_runtime.h>
#include <cstdint>

// Problem constants
#define NSAMP 32768     // 128*256
#define HID   100
#define G4    400
#define INPF  5
#define NPOS  62
#define NREG  16
#define MTILE 32        // samples per block
#define TM    8         // samples per thread
#define NP    (TM/2)    // f32x2 sample-pairs per thread
#define YB    4         // blockDim.y  (YB*TM == MTILE)
#define HSTRIDE 36      // row stride of h_sh in floats (16B-aligned, bank-offset)

__constant__ int c_len[NREG] = {5,5,2,2,6,6,5,5,5,2,2,5,3,3,3,3};
__constant__ int c_off[NREG] = {0,5,10,12,14,20,26,31,36,41,43,45,50,53,56,59};
__constant__ int c_idx[62] = {
    3,0,1,2,4,
    7,8,9,10,11,
    5,6,
    13,12,
    14,15,23,24,32,33,
    22,21,31,30,40,39,
    16,17,18,19,20,
    25,26,27,28,29,
    34,35,36,37,38,
    41,42,
    49,48,
    43,44,45,46,47,
    50,51,57,
    56,55,61,
    52,53,54,
    58,59,60
};

// Prepacked forward Whh: layout [r][k][j][g]  (g fastest, g in {i,f,g,o})
// element = w_hh[r][0][g*100+j][k]
__device__ float g_whhpack[NREG * HID * HID * 4];

// ---------- packed f32x2 helpers ----------
__device__ __forceinline__ unsigned long long pack2(float lo, float hi) {
    unsigned long long r;
    asm("mov.b64 %0, {%1, %2};" : "=l"(r) : "f"(lo), "f"(hi));
    return r;
}
__device__ __forceinline__ void unpack2(unsigned long long v, float& lo, float& hi) {
    asm("mov.b64 {%0, %1}, %2;" : "=f"(lo), "=f"(hi) : "l"(v));
}
__device__ __forceinline__ unsigned long long splat2(float v) {
    unsigned long long r;
    asm("mov.b64 %0, {%1, %1};" : "=l"(r) : "f"(v));
    return r;
}
__device__ __forceinline__ void fma2(unsigned long long& acc,
                                     unsigned long long a,
                                     unsigned long long b) {
    asm("fma.rn.f32x2 %0, %1, %2, %0;" : "+l"(acc) : "l"(a), "l"(b));
}

// ---------- activations ----------
__device__ __forceinline__ float sigm(float x) {
    return __fdividef(1.0f, 1.0f + __expf(-x));
}
__device__ __forceinline__ float tanh_(float x) {
    return fmaf(2.0f, __fdividef(1.0f, 1.0f + __expf(-2.0f * x)), -1.0f);
}

// ---------- weight prepack ----------
__global__ void prepack_kernel(const float* __restrict__ w_hh) {
    int idx = blockIdx.x * blockDim.x + threadIdx.x;
    if (idx >= NREG * HID * HID * 4) return;
    int g = idx & 3;
    int j = (idx >> 2) % HID;
    int k = (idx / (4 * HID)) % HID;
    int r = idx / (4 * HID * HID);
    g_whhpack[idx] = w_hh[((size_t)(r * 2) * G4 + g * HID + j) * HID + k];
}

// ---------- main LSTM kernel ----------
// blockDim = (100, YB). Thread j owns gate rows {j, j+100, j+200, j+300}
// and hidden index j; processes TM samples as NP f32x2 sample-pairs.
// __launch_bounds__(400, 2): cap regs ~78 so TWO CTAs fit per SM (25 warps).
__global__ void __launch_bounds__(100 * YB, 2) lstm_main(
    const float* __restrict__ feat,   // [32768, 62, 5]
    const float* __restrict__ w_ih,   // [16, 2, 400, 5]
    const float* __restrict__ b_ih,   // [16, 2, 400]
    const float* __restrict__ b_hh,   // [16, 2, 400]
    float* __restrict__ out)          // [32768, 16, 200]
{
    // h double-buffered, UNduplicated: one LDS.128 -> 4 samples (2 pairs).
    __shared__ float h_sh[2][HID][HSTRIDE];              // 28.8 KB
    __shared__ float x_sh[6][MTILE][INPF];               //  3.8 KB
    // forward-dir input weights/bias staged in smem (keeps them out of regs)
    __shared__ float wi_sh[4][INPF][HID];                //  8.0 KB
    __shared__ float bi_sh[4][HID];                      //  1.6 KB

    const int j   = threadIdx.x;          // 0..99
    const int y   = threadIdx.y;          // 0..YB-1
    const int tid = y * 100 + j;
    const int r   = blockIdx.y;
    const int m0  = blockIdx.x * MTILE;
    const int T   = c_len[r];
    const int off = c_off[r];
    const int mb  = y * TM;

    // Stage input features for this block's samples and region positions.
    for (int e = tid; e < T * MTILE * INPF; e += 100 * YB) {
        int t   = e / (MTILE * INPF);
        int rem = e - t * (MTILE * INPF);
        int m   = rem / INPF;
        int c   = rem - m * INPF;
        x_sh[t][m][c] =
            feat[((size_t)(m0 + m) * NPOS + c_idx[off + t]) * INPF + c];
    }

    // Stage forward-direction input weights + fused bias into smem.
    // 400*5 weights + 400 biases, cooperatively.
    for (int e = tid; e < G4 * INPF; e += 100 * YB) {
        int row = e / INPF;               // 0..399  (= g*100 + jj)
        int c   = e - row * INPF;
        int g   = row / HID;
        int jj  = row - g * HID;
        wi_sh[g][c][jj] = __ldg(&w_ih[((size_t)(r * 2) * G4 + row) * INPF + c]);
    }
    for (int e = tid; e < G4; e += 100 * YB) {
        int g  = e / HID;
        int jj = e - g * HID;
        int row = (r * 2) * G4 + e;
        bi_sh[g][jj] = __ldg(&b_ih[row]) + __ldg(&b_hh[row]);
    }

    const float* wbase = g_whhpack + ((size_t)r * HID * HID + j) * 4;

    float creg[TM];
#pragma unroll
    for (int p = 0; p < TM; p++) creg[p] = 0.0f;

    __syncthreads();   // x_sh / wi_sh / bi_sh ready

    float hnew[TM];

    for (int t = 0; t < T; t++) {
        // acc[g][q] = {gate_g(sample mb+2q), gate_g(sample mb+2q+1)}
        unsigned long long acc[4][NP];
        {
            float wfi[4][5], bsf[4];
#pragma unroll
            for (int g = 0; g < 4; g++) {
#pragma unroll
                for (int c = 0; c < 5; c++) wfi[g][c] = wi_sh[g][c][j];
                bsf[g] = bi_sh[g][j];
            }
#pragma unroll
            for (int p = 0; p < TM; p++) {
                const float* xv = x_sh[t][mb + p];
                float x0 = xv[0], x1 = xv[1], x2 = xv[2], x3 = xv[3], x4 = xv[4];
                float gv[4];
#pragma unroll
                for (int g = 0; g < 4; g++)
                    gv[g] = bsf[g] + x0*wfi[g][0] + x1*wfi[g][1] + x2*wfi[g][2]
                                   + x3*wfi[g][3] + x4*wfi[g][4];
                if (p & 1) {
                    float lo, hi;
#pragma unroll
                    for (int g = 0; g < 4; g++) {
                        unpack2(acc[g][p >> 1], lo, hi);
                        acc[g][p >> 1] = pack2(lo, gv[g]);
                    }
                } else {
#pragma unroll
                    for (int g = 0; g < 4; g++)
                        acc[g][p >> 1] = pack2(gv[g], 0.0f);
                }
            }
        }

        if (t > 0) {   // h == 0 at t == 0, skip the hh matvec entirely
            const float* hrow = &h_sh[t & 1][0][mb];
#pragma unroll 2
            for (int k = 0; k < HID; k++) {
                // one LDG.128: {w_i, w_f, w_g, w_o} at (k, j)
                float4 w = __ldg(
                    reinterpret_cast<const float4*>(wbase + (size_t)k * G4));
                unsigned long long ws[4];
                ws[0] = splat2(w.x); ws[1] = splat2(w.y);
                ws[2] = splat2(w.z); ws[3] = splat2(w.w);
                // two broadcast LDS.128: h for samples mb..mb+7 as 4 pairs
                const float* hk = hrow + k * HSTRIDE;
                ulonglong2 h01 = *reinterpret_cast<const ulonglong2*>(hk);
                ulonglong2 h23 = *reinterpret_cast<const ulonglong2*>(hk + 4);
                unsigned long long hp[NP] = {h01.x, h01.y, h23.x, h23.y};
#pragma unroll
                for (int g = 0; g < 4; g++) {
#pragma unroll
                    for (int q = 0; q < NP; q++)
                        fma2(acc[g][q], ws[g], hp[q]);
                }
            }
        }

        // LSTM pointwise (thread j owns hidden unit j)
#pragma unroll
        for (int q = 0; q < NP; q++) {
            float gi0, gi1, gf0, gf1, gg0, gg1, go0, go1;
            unpack2(acc[0][q], gi0, gi1);
            unpack2(acc[1][q], gf0, gf1);
            unpack2(acc[2][q], gg0, gg1);
            unpack2(acc[3][q], go0, go1);
            int p0 = 2 * q, p1 = 2 * q + 1;
            creg[p0] = sigm(gf0) * creg[p0] + sigm(gi0) * tanh_(gg0);
            hnew[p0] = sigm(go0) * tanh_(creg[p0]);
            creg[p1] = sigm(gf1) * creg[p1] + sigm(gi1) * tanh_(gg1);
            hnew[p1] = sigm(go1) * tanh_(creg[p1]);
        }

        // Write new h into the OTHER buffer; single barrier per step.
        {
            float4* dst = reinterpret_cast<float4*>(&h_sh[(t + 1) & 1][j][mb]);
            dst[0] = make_float4(hnew[0], hnew[1], hnew[2], hnew[3]);
            dst[1] = make_float4(hnew[4], hnew[5], hnew[6], hnew[7]);
        }
        __syncthreads();   // new h visible; old-buffer reads complete
    }

    // Write forward output h_f
#pragma unroll
    for (int p = 0; p < TM; p++)
        out[(size_t)(m0 + mb + p) * (NREG * 200) + r * 200 + j] = hnew[p];

    // "Backward" LSTM: single step from h=c=0 on the LAST position.
    float wbi[4][5];
    float bsb[4];
#pragma unroll
    for (int g = 0; g < 4; g++) {
        int row = (r * 2 + 1) * G4 + g * HID + j;   // d = 1
#pragma unroll
        for (int c = 0; c < 5; c++) wbi[g][c] = __ldg(&w_ih[(size_t)row * 5 + c]);
        bsb[g] = __ldg(&b_ih[row]) + __ldg(&b_hh[row]);
    }
#pragma unroll
    for (int p = 0; p < TM; p++) {
        const float* xv = x_sh[T - 1][mb + p];
        float x0 = xv[0], x1 = xv[1], x2 = xv[2], x3 = xv[3], x4 = xv[4];
        float gi = bsb[0] + x0*wbi[0][0] + x1*wbi[0][1] + x2*wbi[0][2] + x3*wbi[0][3] + x4*wbi[0][4];
        float gg = bsb[2] + x0*wbi[2][0] + x1*wbi[2][1] + x2*wbi[2][2] + x3*wbi[2][3] + x4*wbi[2][4];
        float go = bsb[3] + x0*wbi[3][0] + x1*wbi[3][1] + x2*wbi[3][2] + x3*wbi[3][3] + x4*wbi[3][4];
        float cb = sigm(gi) * tanh_(gg);
        float hb = sigm(go) * tanh_(cb);
        out[(size_t)(m0 + mb + p) * (NREG * 200) + r * 200 + HID + j] = hb;
    }
}

extern "C" void kernel_launch(void* const* d_in, const int* in_sizes, int n_in,
                              void* d_out, int out_size) {
    const float* feat = (const float*)d_in[0];
    const float* w_ih = (const float*)d_in[1];
    const float* w_hh = (const float*)d_in[2];
    const float* b_ih = (const float*)d_in[3];
    const float* b_hh = (const float*)d_in[4];
    float* out = (float*)d_out;

    int total = NREG * HID * HID * 4;
    prepack_kernel<<<(total + 255) / 256, 256>>>(w_hh);

    dim3 grid(NSAMP / MTILE, NREG);
    dim3 block(100, YB);
    lstm_main<<<grid, block>>>(feat, w_ih, b_ih, b_hh, out);
}

// round 7
// speedup vs baseline: 1.1550x; 1.1550x over previous
#include <cuda_runtime.h>
#include <cstdint>

// Problem constants
#define NSAMP 32768     // 128*256
#define HID   100
#define G4    400
#define INPF  5
#define NPOS  62
#define NREG  16
#define MTILE 32        // samples per block
#define TM    8         // samples per thread
#define NP    (TM/2)    // f32x2 sample-pairs per thread
#define YB    4         // blockDim.y  (YB*TM == MTILE)
#define HSTRIDE 36      // row stride of h_sh in floats (16B-aligned, bank-offset)

__constant__ int c_len[NREG] = {5,5,2,2,6,6,5,5,5,2,2,5,3,3,3,3};
__constant__ int c_off[NREG] = {0,5,10,12,14,20,26,31,36,41,43,45,50,53,56,59};
__constant__ int c_idx[62] = {
    3,0,1,2,4,
    7,8,9,10,11,
    5,6,
    13,12,
    14,15,23,24,32,33,
    22,21,31,30,40,39,
    16,17,18,19,20,
    25,26,27,28,29,
    34,35,36,37,38,
    41,42,
    49,48,
    43,44,45,46,47,
    50,51,57,
    56,55,61,
    52,53,54,
    58,59,60
};

// Prepacked forward Whh: layout [r][k][j][g]  (g fastest, g in {i,f,g,o})
// element = w_hh[r][0][g*100+j][k]
__device__ float g_whhpack[NREG * HID * HID * 4];

// ---------- packed f32x2 helpers ----------
__device__ __forceinline__ unsigned long long pack2(float lo, float hi) {
    unsigned long long r;
    asm("mov.b64 %0, {%1, %2};" : "=l"(r) : "f"(lo), "f"(hi));
    return r;
}
__device__ __forceinline__ void unpack2(unsigned long long v, float& lo, float& hi) {
    asm("mov.b64 {%0, %1}, %2;" : "=f"(lo), "=f"(hi) : "l"(v));
}
__device__ __forceinline__ unsigned long long splat2(float v) {
    unsigned long long r;
    asm("mov.b64 %0, {%1, %1};" : "=l"(r) : "f"(v));
    return r;
}
__device__ __forceinline__ void fma2(unsigned long long& acc,
                                     unsigned long long a,
                                     unsigned long long b) {
    asm("fma.rn.f32x2 %0, %1, %2, %0;" : "+l"(acc) : "l"(a), "l"(b));
}

// ---------- activations (MUFU.TANH path) ----------
__device__ __forceinline__ float tanh_(float x) {
    float r;
    asm("tanh.approx.f32 %0, %1;" : "=f"(r) : "f"(x));
    return r;
}
__device__ __forceinline__ float sigm(float x) {
    return fmaf(0.5f, tanh_(0.5f * x), 0.5f);
}

// ---------- weight prepack ----------
__global__ void prepack_kernel(const float* __restrict__ w_hh) {
    int idx = blockIdx.x * blockDim.x + threadIdx.x;
    if (idx >= NREG * HID * HID * 4) return;
    int g = idx & 3;
    int j = (idx >> 2) % HID;
    int k = (idx / (4 * HID)) % HID;
    int r = idx / (4 * HID * HID);
    g_whhpack[idx] = w_hh[((size_t)(r * 2) * G4 + g * HID + j) * HID + k];
}

// ---------- main LSTM kernel ----------
// blockDim = (100, YB). Thread j owns gate rows {j, j+100, j+200, j+300}
// and hidden index j; processes TM samples as NP f32x2 sample-pairs.
// NO occupancy cap: natural regs (~100) -> 1 CTA/SM; hide latency in-warp.
__global__ void __launch_bounds__(100 * YB) lstm_main(
    const float* __restrict__ feat,   // [32768, 62, 5]
    const float* __restrict__ w_ih,   // [16, 2, 400, 5]
    const float* __restrict__ b_ih,   // [16, 2, 400]
    const float* __restrict__ b_hh,   // [16, 2, 400]
    float* __restrict__ out)          // [32768, 16, 200]
{
    // h double-buffered, UNduplicated: one LDS.128 -> 4 samples (2 pairs).
    __shared__ float h_sh[2][HID][HSTRIDE];              // 28.8 KB
    __shared__ float x_sh[6][MTILE][INPF];               //  3.8 KB
    // forward-dir input weights/bias staged in smem (keeps them out of regs)
    __shared__ float wi_sh[4][INPF][HID];                //  8.0 KB
    __shared__ float bi_sh[4][HID];                      //  1.6 KB

    const int j   = threadIdx.x;          // 0..99
    const int y   = threadIdx.y;          // 0..YB-1
    const int tid = y * 100 + j;
    const int r   = blockIdx.y;
    const int m0  = blockIdx.x * MTILE;
    const int T   = c_len[r];
    const int off = c_off[r];
    const int mb  = y * TM;

    // Stage input features for this block's samples and region positions.
    for (int e = tid; e < T * MTILE * INPF; e += 100 * YB) {
        int t   = e / (MTILE * INPF);
        int rem = e - t * (MTILE * INPF);
        int m   = rem / INPF;
        int c   = rem - m * INPF;
        x_sh[t][m][c] =
            feat[((size_t)(m0 + m) * NPOS + c_idx[off + t]) * INPF + c];
    }

    // Stage forward-direction input weights + fused bias into smem.
    for (int e = tid; e < G4 * INPF; e += 100 * YB) {
        int row = e / INPF;               // 0..399  (= g*100 + jj)
        int c   = e - row * INPF;
        int g   = row / HID;
        int jj  = row - g * HID;
        wi_sh[g][c][jj] = __ldg(&w_ih[((size_t)(r * 2) * G4 + row) * INPF + c]);
    }
    for (int e = tid; e < G4; e += 100 * YB) {
        int g  = e / HID;
        int jj = e - g * HID;
        int row = (r * 2) * G4 + e;
        bi_sh[g][jj] = __ldg(&b_ih[row]) + __ldg(&b_hh[row]);
    }

    const float* wbase = g_whhpack + ((size_t)r * HID * HID + j) * 4;

    float creg[TM];
#pragma unroll
    for (int p = 0; p < TM; p++) creg[p] = 0.0f;

    __syncthreads();   // x_sh / wi_sh / bi_sh ready

    float hnew[TM];

    for (int t = 0; t < T; t++) {
        // acc[g][q] = {gate_g(sample mb+2q), gate_g(sample mb+2q+1)}
        unsigned long long acc[4][NP];
        {
            float wfi[4][5], bsf[4];
#pragma unroll
            for (int g = 0; g < 4; g++) {
#pragma unroll
                for (int c = 0; c < 5; c++) wfi[g][c] = wi_sh[g][c][j];
                bsf[g] = bi_sh[g][j];
            }
#pragma unroll
            for (int p = 0; p < TM; p++) {
                const float* xv = x_sh[t][mb + p];
                float x0 = xv[0], x1 = xv[1], x2 = xv[2], x3 = xv[3], x4 = xv[4];
                float gv[4];
#pragma unroll
                for (int g = 0; g < 4; g++)
                    gv[g] = bsf[g] + x0*wfi[g][0] + x1*wfi[g][1] + x2*wfi[g][2]
                                   + x3*wfi[g][3] + x4*wfi[g][4];
                if (p & 1) {
                    float lo, hi;
#pragma unroll
                    for (int g = 0; g < 4; g++) {
                        unpack2(acc[g][p >> 1], lo, hi);
                        acc[g][p >> 1] = pack2(lo, gv[g]);
                    }
                } else {
#pragma unroll
                    for (int g = 0; g < 4; g++)
                        acc[g][p >> 1] = pack2(gv[g], 0.0f);
                }
            }
        }

        if (t > 0) {   // h == 0 at t == 0, skip the hh matvec entirely
            const float* hrow = &h_sh[t & 1][0][mb];

            // ---- software-pipelined k-loop: prefetch k+1 while FMA-ing k ----
            float4 wcur = __ldg(reinterpret_cast<const float4*>(wbase));
            ulonglong2 h01 = *reinterpret_cast<const ulonglong2*>(hrow);
            ulonglong2 h23 = *reinterpret_cast<const ulonglong2*>(hrow + 4);

#pragma unroll 2
            for (int k = 0; k < HID; k++) {
                float4 wnext;
                ulonglong2 h01n, h23n;
                if (k + 1 < HID) {
                    wnext = __ldg(reinterpret_cast<const float4*>(
                        wbase + (size_t)(k + 1) * G4));
                    const float* hk = hrow + (k + 1) * HSTRIDE;
                    h01n = *reinterpret_cast<const ulonglong2*>(hk);
                    h23n = *reinterpret_cast<const ulonglong2*>(hk + 4);
                }

                unsigned long long ws[4];
                ws[0] = splat2(wcur.x); ws[1] = splat2(wcur.y);
                ws[2] = splat2(wcur.z); ws[3] = splat2(wcur.w);
                unsigned long long hp[NP] = {h01.x, h01.y, h23.x, h23.y};
#pragma unroll
                for (int g = 0; g < 4; g++) {
#pragma unroll
                    for (int q = 0; q < NP; q++)
                        fma2(acc[g][q], ws[g], hp[q]);
                }

                wcur = wnext; h01 = h01n; h23 = h23n;
            }
        }

        // LSTM pointwise (thread j owns hidden unit j)
#pragma unroll
        for (int q = 0; q < NP; q++) {
            float gi0, gi1, gf0, gf1, gg0, gg1, go0, go1;
            unpack2(acc[0][q], gi0, gi1);
            unpack2(acc[1][q], gf0, gf1);
            unpack2(acc[2][q], gg0, gg1);
            unpack2(acc[3][q], go0, go1);
            int p0 = 2 * q, p1 = 2 * q + 1;
            creg[p0] = sigm(gf0) * creg[p0] + sigm(gi0) * tanh_(gg0);
            hnew[p0] = sigm(go0) * tanh_(creg[p0]);
            creg[p1] = sigm(gf1) * creg[p1] + sigm(gi1) * tanh_(gg1);
            hnew[p1] = sigm(go1) * tanh_(creg[p1]);
        }

        // Write new h into the OTHER buffer; single barrier per step.
        {
            float4* dst = reinterpret_cast<float4*>(&h_sh[(t + 1) & 1][j][mb]);
            dst[0] = make_float4(hnew[0], hnew[1], hnew[2], hnew[3]);
            dst[1] = make_float4(hnew[4], hnew[5], hnew[6], hnew[7]);
        }
        __syncthreads();   // new h visible; old-buffer reads complete
    }

    // Write forward output h_f
#pragma unroll
    for (int p = 0; p < TM; p++)
        out[(size_t)(m0 + mb + p) * (NREG * 200) + r * 200 + j] = hnew[p];

    // "Backward" LSTM: single step from h=c=0 on the LAST position.
    float wbi[4][5];
    float bsb[4];
#pragma unroll
    for (int g = 0; g < 4; g++) {
        int row = (r * 2 + 1) * G4 + g * HID + j;   // d = 1
#pragma unroll
        for (int c = 0; c < 5; c++) wbi[g][c] = __ldg(&w_ih[(size_t)row * 5 + c]);
        bsb[g] = __ldg(&b_ih[row]) + __ldg(&b_hh[row]);
    }
#pragma unroll
    for (int p = 0; p < TM; p++) {
        const float* xv = x_sh[T - 1][mb + p];
        float x0 = xv[0], x1 = xv[1], x2 = xv[2], x3 = xv[3], x4 = xv[4];
        float gi = bsb[0] + x0*wbi[0][0] + x1*wbi[0][1] + x2*wbi[0][2] + x3*wbi[0][3] + x4*wbi[0][4];
        float gg = bsb[2] + x0*wbi[2][0] + x1*wbi[2][1] + x2*wbi[2][2] + x3*wbi[2][3] + x4*wbi[2][4];
        float go = bsb[3] + x0*wbi[3][0] + x1*wbi[3][1] + x2*wbi[3][2] + x3*wbi[3][3] + x4*wbi[3][4];
        float cb = sigm(gi) * tanh_(gg);
        float hb = sigm(go) * tanh_(cb);
        out[(size_t)(m0 + mb + p) * (NREG * 200) + r * 200 + HID + j] = hb;
    }
}

extern "C" void kernel_launch(void* const* d_in, const int* in_sizes, int n_in,
                              void* d_out, int out_size) {
    const float* feat = (const float*)d_in[0];
    const float* w_ih = (const float*)d_in[1];
    const float* w_hh = (const float*)d_in[2];
    const float* b_ih = (const float*)d_in[3];
    const float* b_hh = (const float*)d_in[4];
    float* out = (float*)d_out;

    int total = NREG * HID * HID * 4;
    prepack_kernel<<<(total + 255) / 256, 256>>>(w_hh);

    dim3 grid(NSAMP / MTILE, NREG);
    dim3 block(100, YB);
    lstm_main<<<grid, block>>>(feat, w_ih, b_ih, b_hh, out);
}

// round 8
// speedup vs baseline: 1.5948x; 1.3808x over previous
#include <cuda_runtime.h>
#include <cstdint>

// Problem constants
#define NSAMP 32768     // 128*256
#define HID   100
#define G4    400
#define INPF  5
#define NPOS  62
#define NREG  16
#define MTILE 64        // samples per block
#define TM    16        // samples per thread
#define NP    (TM/2)    // f32x2 sample-pairs per thread
#define YB    4         // blockDim.y  (YB*TM == MTILE)
#define HSTRIDE 68      // row stride of h_sh in floats (16B-aligned, bank-offset)

// dynamic smem partition sizes (floats)
#define H_FLOATS   (2 * HID * HSTRIDE)      // 13600
#define X_FLOATS   (6 * MTILE * INPF)       // 1920
#define WI_FLOATS  (4 * INPF * HID)         // 2000
#define BI_FLOATS  (4 * HID)                // 400
#define SMEM_FLOATS (H_FLOATS + X_FLOATS + WI_FLOATS + BI_FLOATS)
#define SMEM_BYTES  (SMEM_FLOATS * 4)       // 71680

__constant__ int c_len[NREG] = {5,5,2,2,6,6,5,5,5,2,2,5,3,3,3,3};
__constant__ int c_off[NREG] = {0,5,10,12,14,20,26,31,36,41,43,45,50,53,56,59};
__constant__ int c_idx[62] = {
    3,0,1,2,4,
    7,8,9,10,11,
    5,6,
    13,12,
    14,15,23,24,32,33,
    22,21,31,30,40,39,
    16,17,18,19,20,
    25,26,27,28,29,
    34,35,36,37,38,
    41,42,
    49,48,
    43,44,45,46,47,
    50,51,57,
    56,55,61,
    52,53,54,
    58,59,60
};

// Prepacked forward Whh: layout [r][k][j][g]  (g fastest, g in {i,f,g,o})
// element = w_hh[r][0][g*100+j][k]
__device__ float g_whhpack[NREG * HID * HID * 4];

// ---------- packed f32x2 helpers ----------
__device__ __forceinline__ unsigned long long pack2(float lo, float hi) {
    unsigned long long r;
    asm("mov.b64 %0, {%1, %2};" : "=l"(r) : "f"(lo), "f"(hi));
    return r;
}
__device__ __forceinline__ void unpack2(unsigned long long v, float& lo, float& hi) {
    asm("mov.b64 {%0, %1}, %2;" : "=f"(lo), "=f"(hi) : "l"(v));
}
__device__ __forceinline__ unsigned long long splat2(float v) {
    unsigned long long r;
    asm("mov.b64 %0, {%1, %1};" : "=l"(r) : "f"(v));
    return r;
}
__device__ __forceinline__ void fma2(unsigned long long& acc,
                                     unsigned long long a,
                                     unsigned long long b) {
    asm("fma.rn.f32x2 %0, %1, %2, %0;" : "+l"(acc) : "l"(a), "l"(b));
}

// ---------- activations (MUFU.TANH path) ----------
__device__ __forceinline__ float tanh_(float x) {
    float r;
    asm("tanh.approx.f32 %0, %1;" : "=f"(r) : "f"(x));
    return r;
}
__device__ __forceinline__ float sigm(float x) {
    return fmaf(0.5f, tanh_(0.5f * x), 0.5f);
}

// ---------- weight prepack ----------
__global__ void prepack_kernel(const float* __restrict__ w_hh) {
    int idx = blockIdx.x * blockDim.x + threadIdx.x;
    if (idx >= NREG * HID * HID * 4) return;
    int g = idx & 3;
    int j = (idx >> 2) % HID;
    int k = (idx / (4 * HID)) % HID;
    int r = idx / (4 * HID * HID);
    g_whhpack[idx] = w_hh[((size_t)(r * 2) * G4 + g * HID + j) * HID + k];
}

// ---------- main LSTM kernel ----------
// blockDim = (100, YB). Thread j owns gate rows {j, j+100, j+200, j+300}
// and hidden index j; processes TM=16 samples as NP=8 f32x2 sample-pairs.
__global__ void __launch_bounds__(100 * YB) lstm_main(
    const float* __restrict__ feat,   // [32768, 62, 5]
    const float* __restrict__ w_ih,   // [16, 2, 400, 5]
    const float* __restrict__ b_ih,   // [16, 2, 400]
    const float* __restrict__ b_hh,   // [16, 2, 400]
    float* __restrict__ out)          // [32768, 16, 200]
{
    extern __shared__ float smem[];
    float* h_sh  = smem;                       // [2][HID][HSTRIDE]
    float* x_sh  = h_sh + H_FLOATS;            // [6][MTILE][INPF]
    float* wi_sh = x_sh + X_FLOATS;            // [4][INPF][HID]
    float* bi_sh = wi_sh + WI_FLOATS;          // [4][HID]

    const int j   = threadIdx.x;          // 0..99
    const int y   = threadIdx.y;          // 0..YB-1
    const int tid = y * 100 + j;
    const int r   = blockIdx.y;
    const int m0  = blockIdx.x * MTILE;
    const int T   = c_len[r];
    const int off = c_off[r];
    const int mb  = y * TM;

    // Stage input features for this block's samples and region positions.
    for (int e = tid; e < T * MTILE * INPF; e += 100 * YB) {
        int t   = e / (MTILE * INPF);
        int rem = e - t * (MTILE * INPF);
        int m   = rem / INPF;
        int c   = rem - m * INPF;
        x_sh[(t * MTILE + m) * INPF + c] =
            feat[((size_t)(m0 + m) * NPOS + c_idx[off + t]) * INPF + c];
    }

    // Stage forward-direction input weights + fused bias into smem.
    for (int e = tid; e < G4 * INPF; e += 100 * YB) {
        int row = e / INPF;               // 0..399  (= g*100 + jj)
        int c   = e - row * INPF;
        int g   = row / HID;
        int jj  = row - g * HID;
        wi_sh[(g * INPF + c) * HID + jj] =
            __ldg(&w_ih[((size_t)(r * 2) * G4 + row) * INPF + c]);
    }
    for (int e = tid; e < G4; e += 100 * YB) {
        int g  = e / HID;
        int jj = e - g * HID;
        int row = (r * 2) * G4 + e;
        bi_sh[g * HID + jj] = __ldg(&b_ih[row]) + __ldg(&b_hh[row]);
    }

    const float* wbase = g_whhpack + ((size_t)r * HID * HID + j) * 4;

    float creg[TM];
#pragma unroll
    for (int p = 0; p < TM; p++) creg[p] = 0.0f;

    __syncthreads();   // x_sh / wi_sh / bi_sh ready

    for (int t = 0; t < T; t++) {
        // acc[g][q] = {gate_g(sample mb+2q), gate_g(sample mb+2q+1)}
        unsigned long long acc[4][NP];
        {
            float wfi[4][5], bsf[4];
#pragma unroll
            for (int g = 0; g < 4; g++) {
#pragma unroll
                for (int c = 0; c < 5; c++) wfi[g][c] = wi_sh[(g * INPF + c) * HID + j];
                bsf[g] = bi_sh[g * HID + j];
            }
#pragma unroll
            for (int q = 0; q < NP; q++) {
                const float* xv0 = &x_sh[(t * MTILE + mb + 2 * q) * INPF];
                const float* xv1 = xv0 + INPF;
                float gv0[4], gv1[4];
#pragma unroll
                for (int g = 0; g < 4; g++) {
                    gv0[g] = bsf[g] + xv0[0]*wfi[g][0] + xv0[1]*wfi[g][1] + xv0[2]*wfi[g][2]
                                    + xv0[3]*wfi[g][3] + xv0[4]*wfi[g][4];
                    gv1[g] = bsf[g] + xv1[0]*wfi[g][0] + xv1[1]*wfi[g][1] + xv1[2]*wfi[g][2]
                                    + xv1[3]*wfi[g][3] + xv1[4]*wfi[g][4];
                    acc[g][q] = pack2(gv0[g], gv1[g]);
                }
            }
        }

        if (t > 0) {   // h == 0 at t == 0, skip the hh matvec entirely
            const float* hrow = h_sh + (t & 1) * (HID * HSTRIDE) + mb;
#pragma unroll 2
            for (int k = 0; k < HID; k++) {
                // one LDG.128: {w_i, w_f, w_g, w_o} at (k, j)
                float4 w = __ldg(
                    reinterpret_cast<const float4*>(wbase + (size_t)k * G4));
                unsigned long long ws[4];
                ws[0] = splat2(w.x); ws[1] = splat2(w.y);
                ws[2] = splat2(w.z); ws[3] = splat2(w.w);
                // four broadcast LDS.128: h for samples mb..mb+15 as 8 pairs
                const float* hk = hrow + k * HSTRIDE;
                ulonglong2 ha = *reinterpret_cast<const ulonglong2*>(hk);
                ulonglong2 hb = *reinterpret_cast<const ulonglong2*>(hk + 4);
                ulonglong2 hc = *reinterpret_cast<const ulonglong2*>(hk + 8);
                ulonglong2 hd = *reinterpret_cast<const ulonglong2*>(hk + 12);
                unsigned long long hp[NP] = {ha.x, ha.y, hb.x, hb.y,
                                             hc.x, hc.y, hd.x, hd.y};
#pragma unroll
                for (int g = 0; g < 4; g++) {
#pragma unroll
                    for (int q = 0; q < NP; q++)
                        fma2(acc[g][q], ws[g], hp[q]);
                }
            }
        }

        // LSTM pointwise (thread j owns hidden unit j); write h to other buffer
        float* hdst = h_sh + ((t + 1) & 1) * (HID * HSTRIDE) + j * HSTRIDE + mb;
#pragma unroll
        for (int q = 0; q < NP; q++) {
            float gi0, gi1, gf0, gf1, gg0, gg1, go0, go1;
            unpack2(acc[0][q], gi0, gi1);
            unpack2(acc[1][q], gf0, gf1);
            unpack2(acc[2][q], gg0, gg1);
            unpack2(acc[3][q], go0, go1);
            int p0 = 2 * q, p1 = 2 * q + 1;
            creg[p0] = sigm(gf0) * creg[p0] + sigm(gi0) * tanh_(gg0);
            creg[p1] = sigm(gf1) * creg[p1] + sigm(gi1) * tanh_(gg1);
            float h0 = sigm(go0) * tanh_(creg[p0]);
            float h1 = sigm(go1) * tanh_(creg[p1]);
            *reinterpret_cast<float2*>(hdst + p0) = make_float2(h0, h1);
        }
        __syncthreads();   // new h visible; old-buffer reads complete
    }

    // Write forward output h_f (re-read own row from final h buffer)
    {
        const float* hfin = h_sh + (T & 1) * (HID * HSTRIDE) + j * HSTRIDE + mb;
#pragma unroll
        for (int p = 0; p < TM; p++)
            out[(size_t)(m0 + mb + p) * (NREG * 200) + r * 200 + j] = hfin[p];
    }

    // "Backward" LSTM: single step from h=c=0 on the LAST position.
    float wbi[4][5];
    float bsb[4];
#pragma unroll
    for (int g = 0; g < 4; g++) {
        int row = (r * 2 + 1) * G4 + g * HID + j;   // d = 1
#pragma unroll
        for (int c = 0; c < 5; c++) wbi[g][c] = __ldg(&w_ih[(size_t)row * 5 + c]);
        bsb[g] = __ldg(&b_ih[row]) + __ldg(&b_hh[row]);
    }
#pragma unroll
    for (int p = 0; p < TM; p++) {
        const float* xv = &x_sh[((T - 1) * MTILE + mb + p) * INPF];
        float x0 = xv[0], x1 = xv[1], x2 = xv[2], x3 = xv[3], x4 = xv[4];
        float gi = bsb[0] + x0*wbi[0][0] + x1*wbi[0][1] + x2*wbi[0][2] + x3*wbi[0][3] + x4*wbi[0][4];
        float gg = bsb[2] + x0*wbi[2][0] + x1*wbi[2][1] + x2*wbi[2][2] + x3*wbi[2][3] + x4*wbi[2][4];
        float go = bsb[3] + x0*wbi[3][0] + x1*wbi[3][1] + x2*wbi[3][2] + x3*wbi[3][3] + x4*wbi[3][4];
        float cb = sigm(gi) * tanh_(gg);
        float hb = sigm(go) * tanh_(cb);
        out[(size_t)(m0 + mb + p) * (NREG * 200) + r * 200 + HID + j] = hb;
    }
}

extern "C" void kernel_launch(void* const* d_in, const int* in_sizes, int n_in,
                              void* d_out, int out_size) {
    const float* feat = (const float*)d_in[0];
    const float* w_ih = (const float*)d_in[1];
    const float* w_hh = (const float*)d_in[2];
    const float* b_ih = (const float*)d_in[3];
    const float* b_hh = (const float*)d_in[4];
    float* out = (float*)d_out;

    static int smem_set = 0;
    if (!smem_set) {
        cudaFuncSetAttribute(lstm_main,
                             cudaFuncAttributeMaxDynamicSharedMemorySize,
                             SMEM_BYTES);
        smem_set = 1;
    }

    int total = NREG * HID * HID * 4;
    prepack_kernel<<<(total + 255) / 256, 256>>>(w_hh);

    dim3 grid(NSAMP / MTILE, NREG);
    dim3 block(100, YB);
    lstm_main<<<grid, block, SMEM_BYTES>>>(feat, w_ih, b_ih, b_hh, out);
}